// round 5
// baseline (speedup 1.0000x reference)
#include <cuda_runtime.h>
#include <cuda_bf16.h>
#include <cstdint>

// ============================================================================
// BayesianLinear on sm_103 (base ISA — tcgen05 blocked by compute_103 target).
// Split-precision bf16 GEMM via mma.sync.m16n8k16:
//   out = x_hi*w_hi + x_hi*w_lo + x_lo*w_hi  (fp32 accum)  + bias
// R4 -> R5:
//   * 4-stage BK=16 cp.async pipeline, ONE __syncthreads per kt, loads
//     issued ahead of compute (3-deep) — decouple the 2 co-resident CTAs.
//   * split-K=2 (grid 2048 -> 6.92 waves) to kill wave quantization;
//     reduction kernel folds partials + bias.
// ============================================================================

#define IN_F   4096
#define OUT_F  4096
#define BATCH  4096

// ---------------- scratch (no cudaMalloc allowed) ----------------
__device__ __align__(16) __nv_bfloat16 g_w_hi[(size_t)OUT_F * IN_F];
__device__ __align__(16) __nv_bfloat16 g_w_lo[(size_t)OUT_F * IN_F];
__device__ __align__(16) __nv_bfloat16 g_x_hi[(size_t)BATCH * IN_F];
__device__ __align__(16) __nv_bfloat16 g_x_lo[(size_t)BATCH * IN_F];
__device__ __align__(16) float         g_bias[OUT_F];
__device__ __align__(16) float         g_part[2][(size_t)BATCH * OUT_F];

// ---------------- helpers ----------------
__device__ __forceinline__ uint32_t smem_to_u32(const void* p) {
    uint32_t a;
    asm("{ .reg .u64 t; cvta.to.shared.u64 t, %1; cvt.u32.u64 %0, t; }" : "=r"(a) : "l"(p));
    return a;
}

__device__ __forceinline__ void cp16(uint32_t saddr, const void* gptr) {
    size_t ga = __cvta_generic_to_global(gptr);
    asm volatile("cp.async.cg.shared.global [%0], [%1], 16;"
                 :: "r"(saddr), "l"(ga) : "memory");
}
#define CP_COMMIT() asm volatile("cp.async.commit_group;" ::: "memory")
#define CP_WAIT2()  asm volatile("cp.async.wait_group 2;" ::: "memory")

__device__ __forceinline__ void ldsm_x4(uint32_t (&r)[4], uint32_t saddr) {
    asm volatile("ldmatrix.sync.aligned.m8n8.x4.shared.b16 {%0,%1,%2,%3}, [%4];"
                 : "=r"(r[0]), "=r"(r[1]), "=r"(r[2]), "=r"(r[3]) : "r"(saddr));
}

__device__ __forceinline__ void mma_bf16(float (&d)[4], const uint32_t (&a)[4],
                                         uint32_t b0, uint32_t b1) {
    asm volatile(
        "mma.sync.aligned.m16n8k16.row.col.f32.bf16.bf16.f32 "
        "{%0,%1,%2,%3}, {%4,%5,%6,%7}, {%8,%9}, {%0,%1,%2,%3};"
        : "+f"(d[0]), "+f"(d[1]), "+f"(d[2]), "+f"(d[3])
        : "r"(a[0]), "r"(a[1]), "r"(a[2]), "r"(a[3]), "r"(b0), "r"(b1));
}

__device__ __forceinline__ uint32_t pack_bf16x2(float a, float b) {
    __nv_bfloat16 ha = __float2bfloat16(a);
    __nv_bfloat16 hb = __float2bfloat16(b);
    return (uint32_t)__bfloat16_as_ushort(ha) | ((uint32_t)__bfloat16_as_ushort(hb) << 16);
}

__device__ __forceinline__ void split4(const float (&w)[4], uint2& ph, uint2& pl) {
    float hi[4], lo[4];
#pragma unroll
    for (int j = 0; j < 4; j++) {
        __nv_bfloat16 h = __float2bfloat16(w[j]);
        hi[j] = __bfloat162float(h);
        lo[j] = w[j] - hi[j];
    }
    ph = make_uint2(pack_bf16x2(hi[0], hi[1]), pack_bf16x2(hi[2], hi[3]));
    pl = make_uint2(pack_bf16x2(lo[0], lo[1]), pack_bf16x2(lo[2], lo[3]));
}

// ============================================================================
// Pass 1: parameter materialization
// ============================================================================
__global__ void __launch_bounds__(256) prep_weight_kernel(
    const float* __restrict__ mu, const float* __restrict__ rho,
    const float* __restrict__ eps)
{
    size_t i4 = (size_t)blockIdx.x * blockDim.x + threadIdx.x;
    const float4 m = ((const float4*)mu)[i4];
    const float4 r = ((const float4*)rho)[i4];
    const float4 e = ((const float4*)eps)[i4];
    float w[4];
    w[0] = m.x + (log1pf(expf(r.x)) + 1e-8f) * e.x;
    w[1] = m.y + (log1pf(expf(r.y)) + 1e-8f) * e.y;
    w[2] = m.z + (log1pf(expf(r.z)) + 1e-8f) * e.z;
    w[3] = m.w + (log1pf(expf(r.w)) + 1e-8f) * e.w;
    uint2 ph, pl;
    split4(w, ph, pl);
    ((uint2*)g_w_hi)[i4] = ph;
    ((uint2*)g_w_lo)[i4] = pl;
}

__global__ void __launch_bounds__(256) prep_x_kernel(const float* __restrict__ x)
{
    size_t i4 = (size_t)blockIdx.x * blockDim.x + threadIdx.x;
    const float4 v = ((const float4*)x)[i4];
    float w[4] = {v.x, v.y, v.z, v.w};
    uint2 ph, pl;
    split4(w, ph, pl);
    ((uint2*)g_x_hi)[i4] = ph;
    ((uint2*)g_x_lo)[i4] = pl;
}

__global__ void __launch_bounds__(256) prep_bias_kernel(
    const float* __restrict__ bmu, const float* __restrict__ brho,
    const float* __restrict__ beps)
{
    int i = blockIdx.x * blockDim.x + threadIdx.x;
    if (i < OUT_F)
        g_bias[i] = bmu[i] + (log1pf(expf(brho[i])) + 1e-8f) * beps[i];
}

// ============================================================================
// Pass 2: GEMM. CTA 128x128, BK=16, 4-stage cp.async ring, 1 sync/kt,
// 8 warps (2M x 4N), 2 CTAs/SM, split-K=2 over blockIdx.z.
// ============================================================================
#define BM 128
#define BN 128
#define BK 16
#define KPAD 24          // bf16/row -> 48 B rows: 16B-aligned & conflict-free
#define ARR_B (128 * 48) // 6144 B per array
#define OFF_AH 0
#define OFF_AL (1 * ARR_B)
#define OFF_BH (2 * ARR_B)
#define OFF_BL (3 * ARR_B)
#define STAGE_BYTES (4 * ARR_B)   // 24576
#define NSTAGE 4
#define SMEM_SIZE (NSTAGE * STAGE_BYTES)   // 98304
#define KSPLIT 2
#define KHALF (IN_F / KSPLIT)     // 2048
#define NT (KHALF / BK)           // 128

__global__ void __launch_bounds__(256, 2) gemm_kernel()
{
    extern __shared__ char smem[];
    const uint32_t sbase = smem_to_u32(smem);
    const int tid  = threadIdx.x;
    const int lane = tid & 31;
    const int w    = tid >> 5;
    const int wm   = w >> 2;   // 0..1
    const int wn   = w & 3;    // 0..3
    const int m0 = blockIdx.y * BM;
    const int n0 = blockIdx.x * BN;
    const int kz = blockIdx.z;
    const int kbase = kz * KHALF;

    float acc[4][4][4];
#pragma unroll
    for (int f = 0; f < 4; f++)
#pragma unroll
        for (int n = 0; n < 4; n++)
#pragma unroll
            for (int q = 0; q < 4; q++) acc[f][n][q] = 0.0f;

    // cp.async coords: thread t -> row = t>>1 (0..127), chunk c = t&1 (16 B)
    const int lrow = tid >> 1;
    const int lc8  = (tid & 1) << 3;          // bf16 offset within row
    const uint32_t lso = (uint32_t)(lrow * 48 + lc8 * 2);
    const size_t gxa = (size_t)(m0 + lrow) * IN_F + kbase + lc8;
    const size_t gwa = (size_t)(n0 + lrow) * IN_F + kbase + lc8;

    // ldmatrix fragment bases (bf16 units)
    const uint32_t a_base = (uint32_t)((wm * 64 + (lane & 15)) * KPAD + (lane >> 4) * 8);
    const uint32_t b_base = (uint32_t)((wn * 32 + (lane & 7) + ((lane >> 4) & 1) * 8) * KPAD
                                       + ((lane >> 3) & 1) * 8);

#define LOAD_STAGE(ST, KT) do {                                    \
    uint32_t sb_ = sbase + (uint32_t)(ST) * STAGE_BYTES + lso;     \
    size_t ko_ = (size_t)(KT) * BK;                                \
    cp16(sb_ + OFF_AH, g_x_hi + gxa + ko_);                        \
    cp16(sb_ + OFF_AL, g_x_lo + gxa + ko_);                        \
    cp16(sb_ + OFF_BH, g_w_hi + gwa + ko_);                        \
    cp16(sb_ + OFF_BL, g_w_lo + gwa + ko_);                        \
} while (0)

    LOAD_STAGE(0, 0); CP_COMMIT();
    LOAD_STAGE(1, 1); CP_COMMIT();
    LOAD_STAGE(2, 2); CP_COMMIT();

#pragma unroll 4
    for (int kt = 0; kt < NT; kt++) {
        CP_WAIT2();            // stage kt%4 complete (<=2 younger pending)
        __syncthreads();       // publish; also: all warps done reading (kt-1)%4

        // load into (kt+3)%4 == (kt-1)%4 — safe after the barrier above
        if (kt + 3 < NT) LOAD_STAGE((kt + 3) & 3, kt + 3);
        CP_COMMIT();           // always commit to keep group accounting fixed

        const uint32_t sb = sbase + (uint32_t)(kt & 3) * STAGE_BYTES;

        // B fragments (hi+lo): 16 regs
        uint32_t bh[2][4], bl[2][4];
#pragma unroll
        for (int p = 0; p < 2; p++) {
            uint32_t bo = sb + OFF_BH + (b_base + (uint32_t)(p * 16 * KPAD)) * 2;
            ldsm_x4(bh[p], bo);
            ldsm_x4(bl[p], bo + (OFF_BL - OFF_BH));
        }
        // A fragments per f
#pragma unroll
        for (int f = 0; f < 4; f++) {
            uint32_t ah[4], al[4];
            uint32_t ao = sb + OFF_AH + (a_base + (uint32_t)(f * 16 * KPAD)) * 2;
            ldsm_x4(ah, ao);
            ldsm_x4(al, ao + (OFF_AL - OFF_AH));
#pragma unroll
            for (int n = 0; n < 4; n++) {
                const int p = n >> 1, q = (n & 1) * 2;
                mma_bf16(acc[f][n], ah, bh[p][q], bh[p][q + 1]);
            }
#pragma unroll
            for (int n = 0; n < 4; n++) {
                const int p = n >> 1, q = (n & 1) * 2;
                mma_bf16(acc[f][n], ah, bl[p][q], bl[p][q + 1]);
            }
#pragma unroll
            for (int n = 0; n < 4; n++) {
                const int p = n >> 1, q = (n & 1) * 2;
                mma_bf16(acc[f][n], al, bh[p][q], bh[p][q + 1]);
            }
        }
    }

    // ---- epilogue: write fp32 partial (no bias; folded in reduction) ----
    float* part = g_part[kz];
#pragma unroll
    for (int n = 0; n < 4; n++) {
        const int c = n0 + wn * 32 + n * 8 + (lane & 3) * 2;
#pragma unroll
        for (int f = 0; f < 4; f++) {
            const int r = m0 + wm * 64 + f * 16 + (lane >> 2);
            float2 v0, v1;
            v0.x = acc[f][n][0]; v0.y = acc[f][n][1];
            v1.x = acc[f][n][2]; v1.y = acc[f][n][3];
            *(float2*)(part + (size_t)r * OUT_F + c) = v0;
            *(float2*)(part + (size_t)(r + 8) * OUT_F + c) = v1;
        }
    }
}

// ============================================================================
// Pass 3: reduction — out = part0 + part1 + bias
// ============================================================================
__global__ void __launch_bounds__(256) reduce_kernel(float* __restrict__ out)
{
    size_t i4 = (size_t)blockIdx.x * blockDim.x + threadIdx.x;
    const float4 a = ((const float4*)g_part[0])[i4];
    const float4 b = ((const float4*)g_part[1])[i4];
    const float4 bs = ((const float4*)g_bias)[i4 & (OUT_F / 4 - 1)];
    float4 v;
    v.x = a.x + b.x + bs.x;
    v.y = a.y + b.y + bs.y;
    v.z = a.z + b.z + bs.z;
    v.w = a.w + b.w + bs.w;
    ((float4*)out)[i4] = v;
}

// ============================================================================
// launch
// ============================================================================
extern "C" void kernel_launch(void* const* d_in, const int* in_sizes, int n_in,
                              void* d_out, int out_size)
{
    const float* x    = (const float*)d_in[0];
    const float* wmu  = (const float*)d_in[1];
    const float* wrho = (const float*)d_in[2];
    const float* bmu  = (const float*)d_in[3];
    const float* brho = (const float*)d_in[4];
    const float* weps = (const float*)d_in[5];
    const float* beps = (const float*)d_in[6];
    float* out = (float*)d_out;

    prep_weight_kernel<<<(OUT_F * (IN_F / 4)) / 256, 256>>>(wmu, wrho, weps);
    prep_x_kernel<<<(BATCH * (IN_F / 4)) / 256, 256>>>(x);
    prep_bias_kernel<<<OUT_F / 256, 256>>>(bmu, brho, beps);

    static bool attr_set = false;
    if (!attr_set) {
        cudaFuncSetAttribute(gemm_kernel, cudaFuncAttributeMaxDynamicSharedMemorySize, SMEM_SIZE);
        attr_set = true;
    }
    dim3 grid(OUT_F / BN, BATCH / BM, KSPLIT);
    gemm_kernel<<<grid, 256, SMEM_SIZE>>>();

    reduce_kernel<<<((size_t)BATCH * OUT_F / 4) / 256, 256>>>(out);
}

// round 6
// speedup vs baseline: 2.7737x; 2.7737x over previous
#include <cuda_runtime.h>
#include <cuda_fp16.h>
#include <cstdint>

// ============================================================================
// BayesianLinear on sm_103 (base ISA — tcgen05 blocked by compute_103 target).
// R5 -> R6: single-pass fp16 GEMM (validated error model says rel_err ~4e-4,
// under the 1e-3 threshold). 3x fewer HMMAs than the bf16 split scheme:
//   w = mu + softplus(rho)*eps -> fp16;  x -> fp16
//   out = x_f16 @ w_f16^T  (fp32 accum)  + bias
// CTA 128x128, BK=32, 4-stage cp.async ring, one __syncthreads per kt,
// 8 warps (2M x 4N), 2 CTAs/SM.
// ============================================================================

#define IN_F   4096
#define OUT_F  4096
#define BATCH  4096

// ---------------- scratch (no cudaMalloc allowed) ----------------
__device__ __align__(16) __half g_w_h[(size_t)OUT_F * IN_F];
__device__ __align__(16) __half g_x_h[(size_t)BATCH * IN_F];
__device__ __align__(16) float  g_bias[OUT_F];

// ---------------- helpers ----------------
__device__ __forceinline__ uint32_t smem_to_u32(const void* p) {
    uint32_t a;
    asm("{ .reg .u64 t; cvta.to.shared.u64 t, %1; cvt.u32.u64 %0, t; }" : "=r"(a) : "l"(p));
    return a;
}

__device__ __forceinline__ void cp16(uint32_t saddr, const void* gptr) {
    size_t ga = __cvta_generic_to_global(gptr);
    asm volatile("cp.async.cg.shared.global [%0], [%1], 16;"
                 :: "r"(saddr), "l"(ga) : "memory");
}
#define CP_COMMIT() asm volatile("cp.async.commit_group;" ::: "memory")
#define CP_WAIT2()  asm volatile("cp.async.wait_group 2;" ::: "memory")

__device__ __forceinline__ void ldsm_x4(uint32_t (&r)[4], uint32_t saddr) {
    asm volatile("ldmatrix.sync.aligned.m8n8.x4.shared.b16 {%0,%1,%2,%3}, [%4];"
                 : "=r"(r[0]), "=r"(r[1]), "=r"(r[2]), "=r"(r[3]) : "r"(saddr));
}

__device__ __forceinline__ void mma_f16(float (&d)[4], const uint32_t (&a)[4],
                                        uint32_t b0, uint32_t b1) {
    asm volatile(
        "mma.sync.aligned.m16n8k16.row.col.f32.f16.f16.f32 "
        "{%0,%1,%2,%3}, {%4,%5,%6,%7}, {%8,%9}, {%0,%1,%2,%3};"
        : "+f"(d[0]), "+f"(d[1]), "+f"(d[2]), "+f"(d[3])
        : "r"(a[0]), "r"(a[1]), "r"(a[2]), "r"(a[3]), "r"(b0), "r"(b1));
}

__device__ __forceinline__ uint32_t pack_h2(float a, float b) {
    __half ha = __float2half_rn(a);
    __half hb = __float2half_rn(b);
    return (uint32_t)__half_as_ushort(ha) | ((uint32_t)__half_as_ushort(hb) << 16);
}

// ============================================================================
// Pass 1: parameter materialization (fp16)
// ============================================================================
__global__ void __launch_bounds__(256) prep_weight_kernel(
    const float* __restrict__ mu, const float* __restrict__ rho,
    const float* __restrict__ eps)
{
    size_t i4 = (size_t)blockIdx.x * blockDim.x + threadIdx.x;
    const float4 m = ((const float4*)mu)[i4];
    const float4 r = ((const float4*)rho)[i4];
    const float4 e = ((const float4*)eps)[i4];
    float w0 = m.x + (log1pf(expf(r.x)) + 1e-8f) * e.x;
    float w1 = m.y + (log1pf(expf(r.y)) + 1e-8f) * e.y;
    float w2 = m.z + (log1pf(expf(r.z)) + 1e-8f) * e.z;
    float w3 = m.w + (log1pf(expf(r.w)) + 1e-8f) * e.w;
    ((uint2*)g_w_h)[i4] = make_uint2(pack_h2(w0, w1), pack_h2(w2, w3));
}

__global__ void __launch_bounds__(256) prep_x_kernel(const float* __restrict__ x)
{
    size_t i4 = (size_t)blockIdx.x * blockDim.x + threadIdx.x;
    const float4 v = ((const float4*)x)[i4];
    ((uint2*)g_x_h)[i4] = make_uint2(pack_h2(v.x, v.y), pack_h2(v.z, v.w));
}

__global__ void __launch_bounds__(256) prep_bias_kernel(
    const float* __restrict__ bmu, const float* __restrict__ brho,
    const float* __restrict__ beps)
{
    int i = blockIdx.x * blockDim.x + threadIdx.x;
    if (i < OUT_F)
        g_bias[i] = bmu[i] + (log1pf(expf(brho[i])) + 1e-8f) * beps[i];
}

// ============================================================================
// Pass 2: GEMM. CTA 128x128, BK=32 fp16, 4-stage ring, 1 sync/kt,
// 8 warps (2M x 4N, warp 64x32), 2 CTAs/SM.
// ============================================================================
#define BM 128
#define BN 128
#define BK 32
#define KPAD 40                   // fp16/row -> 80 B rows, conflict-free ldmatrix
#define ARR_B (128 * 80)          // 10240 B per array
#define OFF_A 0
#define OFF_B ARR_B
#define STAGE_BYTES (2 * ARR_B)   // 20480
#define NSTAGE 4
#define SMEM_SIZE (NSTAGE * STAGE_BYTES)   // 81920
#define NT (IN_F / BK)            // 128

__global__ void __launch_bounds__(256, 2) gemm_kernel(float* __restrict__ out)
{
    extern __shared__ char smem[];
    const uint32_t sbase = smem_to_u32(smem);
    const int tid  = threadIdx.x;
    const int lane = tid & 31;
    const int w    = tid >> 5;
    const int wm   = w >> 2;   // 0..1
    const int wn   = w & 3;    // 0..3
    const int m0 = blockIdx.y * BM;
    const int n0 = blockIdx.x * BN;

    float acc[4][4][4];
#pragma unroll
    for (int f = 0; f < 4; f++)
#pragma unroll
        for (int n = 0; n < 4; n++)
#pragma unroll
            for (int q = 0; q < 4; q++) acc[f][n][q] = 0.0f;

    // cp.async coords: thread t -> rows (t>>2) and (t>>2)+64; 16B chunk (t&3)
    const int lrow = tid >> 2;
    const int lc8  = (tid & 3) << 3;          // fp16 offset within row
    const uint32_t lso0 = (uint32_t)(lrow * 80 + lc8 * 2);
    const uint32_t lso1 = (uint32_t)((lrow + 64) * 80 + lc8 * 2);
    const size_t gx0 = (size_t)(m0 + lrow) * IN_F + lc8;
    const size_t gx1 = (size_t)(m0 + lrow + 64) * IN_F + lc8;
    const size_t gw0 = (size_t)(n0 + lrow) * IN_F + lc8;
    const size_t gw1 = (size_t)(n0 + lrow + 64) * IN_F + lc8;

    // ldmatrix fragment bases (fp16 units)
    const uint32_t a_base = (uint32_t)((wm * 64 + (lane & 15)) * KPAD + (lane >> 4) * 8);
    const uint32_t b_base = (uint32_t)((wn * 32 + (lane & 7) + ((lane >> 4) & 1) * 8) * KPAD
                                       + ((lane >> 3) & 1) * 8);

#define LOAD_STAGE(ST, KT) do {                                    \
    uint32_t sb_ = sbase + (uint32_t)(ST) * STAGE_BYTES;           \
    size_t ko_ = (size_t)(KT) * BK;                                \
    cp16(sb_ + OFF_A + lso0, g_x_h + gx0 + ko_);                   \
    cp16(sb_ + OFF_A + lso1, g_x_h + gx1 + ko_);                   \
    cp16(sb_ + OFF_B + lso0, g_w_h + gw0 + ko_);                   \
    cp16(sb_ + OFF_B + lso1, g_w_h + gw1 + ko_);                   \
} while (0)

    LOAD_STAGE(0, 0); CP_COMMIT();
    LOAD_STAGE(1, 1); CP_COMMIT();
    LOAD_STAGE(2, 2); CP_COMMIT();

#pragma unroll 4
    for (int kt = 0; kt < NT; kt++) {
        CP_WAIT2();            // stage kt%4 complete
        __syncthreads();       // publish + all warps done reading (kt-1)%4

        if (kt + 3 < NT) LOAD_STAGE((kt + 3) & 3, kt + 3);
        CP_COMMIT();           // fixed group accounting

        const uint32_t sb = sbase + (uint32_t)(kt & 3) * STAGE_BYTES;

#pragma unroll
        for (int ks = 0; ks < 2; ks++) {
            uint32_t b[2][4];
#pragma unroll
            for (int p = 0; p < 2; p++)
                ldsm_x4(b[p], sb + OFF_B + (b_base + (uint32_t)(p * 16 * KPAD + ks * 16)) * 2);
#pragma unroll
            for (int f = 0; f < 4; f++) {
                uint32_t a[4];
                ldsm_x4(a, sb + OFF_A + (a_base + (uint32_t)(f * 16 * KPAD + ks * 16)) * 2);
#pragma unroll
                for (int n = 0; n < 4; n++) {
                    const int p = n >> 1, q = (n & 1) * 2;
                    mma_f16(acc[f][n], a, b[p][q], b[p][q + 1]);
                }
            }
        }
    }

    // ---- epilogue: add bias, write out ----
#pragma unroll
    for (int n = 0; n < 4; n++) {
        const int c = n0 + wn * 32 + n * 8 + (lane & 3) * 2;
        const float2 bs = *(const float2*)(g_bias + c);
#pragma unroll
        for (int f = 0; f < 4; f++) {
            const int r = m0 + wm * 64 + f * 16 + (lane >> 2);
            float2 v0, v1;
            v0.x = acc[f][n][0] + bs.x; v0.y = acc[f][n][1] + bs.y;
            v1.x = acc[f][n][2] + bs.x; v1.y = acc[f][n][3] + bs.y;
            *(float2*)(out + (size_t)r * OUT_F + c) = v0;
            *(float2*)(out + (size_t)(r + 8) * OUT_F + c) = v1;
        }
    }
}

// ============================================================================
// launch
// ============================================================================
extern "C" void kernel_launch(void* const* d_in, const int* in_sizes, int n_in,
                              void* d_out, int out_size)
{
    const float* x    = (const float*)d_in[0];
    const float* wmu  = (const float*)d_in[1];
    const float* wrho = (const float*)d_in[2];
    const float* bmu  = (const float*)d_in[3];
    const float* brho = (const float*)d_in[4];
    const float* weps = (const float*)d_in[5];
    const float* beps = (const float*)d_in[6];
    float* out = (float*)d_out;

    prep_weight_kernel<<<(OUT_F * (IN_F / 4)) / 256, 256>>>(wmu, wrho, weps);
    prep_x_kernel<<<(BATCH * (IN_F / 4)) / 256, 256>>>(x);
    prep_bias_kernel<<<OUT_F / 256, 256>>>(bmu, brho, beps);

    static bool attr_set = false;
    if (!attr_set) {
        cudaFuncSetAttribute(gemm_kernel, cudaFuncAttributeMaxDynamicSharedMemorySize, SMEM_SIZE);
        attr_set = true;
    }
    dim3 grid(OUT_F / BN, BATCH / BM);
    gemm_kernel<<<grid, 256, SMEM_SIZE>>>(out);
}